// round 2
// baseline (speedup 1.0000x reference)
#include <cuda_runtime.h>
#include <cuda_bf16.h>
#include <math.h>

#define H    512
#define NH   8
#define DH   64
#define TCTX 10
#define FFD  2048
#define NPREDC 26
#define MAXB 16
#define MAXF 5

// ------------------------- device scratch -------------------------
__device__ float g_x    [MAXB * MAXF * H];
__device__ float g_qkv  [MAXB * MAXF * 3 * H];
__device__ float g_kv   [MAXB * TCTX * 2 * H];
__device__ float g_attno[MAXB * MAXF * H];
__device__ float g_y    [MAXB * MAXF * H];
__device__ float g_h    [MAXB * MAXF * FFD];
__device__ float g_ctx  [MAXB * MAXF * H];
__device__ float g_Sa   [MAXB * 20 * H];
__device__ float g_Sb   [MAXB * 20 * H];
__device__ float g_Sc   [MAXB * MAXF * H];
__device__ float g_Wc   [27 * H];
__device__ float g_bc   [27];

__device__ __forceinline__ float gelu_f(float x) {
    return 0.5f * x * (1.0f + erff(x * 0.70710678118654752440f));
}

// ------------------------- broadcast queries -------------------------
__global__ void bcast_kernel(const float* __restrict__ fq, float* __restrict__ x, int Fh) {
    int row = blockIdx.x;          // b*Fh + f
    int f = row % Fh;
    int tid = threadIdx.x;         // 128
    #pragma unroll
    for (int i = 0; i < 4; i++) {
        int c = tid + i * 128;
        x[row * H + c] = fq[f * H + c];
    }
}

// ------------------------- generic GEMM: C = A @ W^T (+bias)(+act)(+res) ----
// A: (M,K) lda; W: (N,K) row-major with row stride ldw; C: (M,N) ldc
// grid (M/16, N/64), 256 threads. M%16==0, N%64==0, K%32==0 guaranteed.
__global__ __launch_bounds__(256) void gemm_kernel(
    const float* __restrict__ A, int lda,
    const float* __restrict__ W, int ldw,
    const float* __restrict__ bias,
    const float* __restrict__ res,
    float* __restrict__ C, int ldc,
    int K, int act)
{
    __shared__ float As[16][33];
    __shared__ float Ws[64][33];
    int tid = threadIdx.x;
    int row0 = blockIdx.x * 16;
    int n0   = blockIdx.y * 64;
    int r  = tid >> 4;            // 0..15
    int c0 = (tid & 15) << 2;     // 0..60
    int ar = tid >> 4;
    int ak = (tid & 15) << 1;
    float acc0 = 0.f, acc1 = 0.f, acc2 = 0.f, acc3 = 0.f;

    for (int k0 = 0; k0 < K; k0 += 32) {
        float2 av = *(const float2*)&A[(row0 + ar) * lda + k0 + ak];
        As[ar][ak]     = av.x;
        As[ar][ak + 1] = av.y;
        #pragma unroll
        for (int q = 0; q < 4; q++) {
            int f2 = q * 256 + tid;
            int wn = f2 >> 4;
            int wk = (f2 & 15) << 1;
            float2 wv = *(const float2*)&W[(n0 + wn) * ldw + k0 + wk];
            Ws[wn][wk]     = wv.x;
            Ws[wn][wk + 1] = wv.y;
        }
        __syncthreads();
        #pragma unroll
        for (int kk = 0; kk < 32; kk++) {
            float a = As[r][kk];
            acc0 += a * Ws[c0    ][kk];
            acc1 += a * Ws[c0 + 1][kk];
            acc2 += a * Ws[c0 + 2][kk];
            acc3 += a * Ws[c0 + 3][kk];
        }
        __syncthreads();
    }

    int row = row0 + r;
    float v[4] = {acc0, acc1, acc2, acc3};
    #pragma unroll
    for (int j = 0; j < 4; j++) {
        int n = n0 + c0 + j;
        float x = v[j];
        if (bias) x += bias[n];
        if (act == 1) x = gelu_f(x);
        if (res) x += res[row * ldc + n];
        C[row * ldc + n] = x;
    }
}

// ------------------------- attention (tiny T) -------------------------
// grid = B*NH blocks; block = 32*Tq threads; warp qi handles query row qi.
// q row index = b*Tq+qi (stride ldq); kv row index = b*Tk+k (stride ldkv).
__global__ void attn_kernel(
    const float* __restrict__ Q, int ldq,
    const float* __restrict__ Kp, const float* __restrict__ Vp, int ldkv,
    float* __restrict__ O, int Tq, int Tk)
{
    int b = blockIdx.x / NH;
    int h = blockIdx.x % NH;
    int qi = threadIdx.x >> 5;
    int lane = threadIdx.x & 31;

    const float* qrow = Q + (b * Tq + qi) * ldq + h * DH;
    float q0 = qrow[lane], q1 = qrow[lane + 32];

    float s[TCTX];
    #pragma unroll
    for (int k = 0; k < TCTX; k++) {
        if (k < Tk) {
            const float* krow = Kp + (b * Tk + k) * ldkv + h * DH;
            float p = q0 * krow[lane] + q1 * krow[lane + 32];
            #pragma unroll
            for (int off = 16; off; off >>= 1) p += __shfl_xor_sync(0xffffffffu, p, off);
            s[k] = p * 0.125f;   // 1/sqrt(64)
        }
    }
    float mx = -1e30f;
    #pragma unroll
    for (int k = 0; k < TCTX; k++) if (k < Tk) mx = fmaxf(mx, s[k]);
    float sum = 0.f;
    #pragma unroll
    for (int k = 0; k < TCTX; k++) if (k < Tk) { s[k] = expf(s[k] - mx); sum += s[k]; }
    float inv = 1.f / sum;
    float o0 = 0.f, o1 = 0.f;
    #pragma unroll
    for (int k = 0; k < TCTX; k++) {
        if (k < Tk) {
            const float* vrow = Vp + (b * Tk + k) * ldkv + h * DH;
            float a = s[k] * inv;
            o0 += a * vrow[lane];
            o1 += a * vrow[lane + 32];
        }
    }
    float* orow = O + (b * Tq + qi) * H + h * DH;
    orow[lane]      = o0;
    orow[lane + 32] = o1;
}

// ------------------------- row LayerNorm (H=512) -------------------------
__global__ void ln_kernel(const float* __restrict__ src, float* __restrict__ dst,
                          const float* __restrict__ w, const float* __restrict__ b)
{
    __shared__ float red[4];
    int row = blockIdx.x;
    int tid = threadIdx.x;         // 128
    int lane = tid & 31, wid = tid >> 5;
    const float* x = src + row * H;

    float v[4];
    float s = 0.f;
    #pragma unroll
    for (int i = 0; i < 4; i++) { v[i] = x[tid + i * 128]; s += v[i]; }
    #pragma unroll
    for (int o = 16; o; o >>= 1) s += __shfl_xor_sync(0xffffffffu, s, o);
    if (lane == 0) red[wid] = s;
    __syncthreads();
    float mean = (red[0] + red[1] + red[2] + red[3]) * (1.0f / H);
    __syncthreads();

    float q = 0.f;
    #pragma unroll
    for (int i = 0; i < 4; i++) { float d = v[i] - mean; q += d * d; }
    #pragma unroll
    for (int o = 16; o; o >>= 1) q += __shfl_xor_sync(0xffffffffu, q, o);
    if (lane == 0) red[wid] = q;
    __syncthreads();
    float var = (red[0] + red[1] + red[2] + red[3]) * (1.0f / H);
    float inv = 1.0f / sqrtf(var + 1e-5f);

    #pragma unroll
    for (int i = 0; i < 4; i++) {
        int c = tid + i * 128;
        dst[row * H + c] = (v[i] - mean) * inv * w[c] + b[c];
    }
}

// ------------------------- Wc = [pred_w;ex_w] @ pe2_w, bc fold ------------
__global__ void wc_kernel(const float* __restrict__ pred_w, const float* __restrict__ pred_b,
                          const float* __restrict__ ex_w, const float* __restrict__ ex_b,
                          const float* __restrict__ pe2_w, const float* __restrict__ pe2_b,
                          float* __restrict__ Wc, float* __restrict__ bc)
{
    int rr = blockIdx.x;                       // 0..26
    int c = blockIdx.y * 64 + threadIdx.x;     // 0..511
    const float* Prow = (rr < NPREDC) ? (pred_w + rr * H) : ex_w;
    float acc = 0.f;
    for (int n = 0; n < H; n++) acc += Prow[n] * pe2_w[n * H + c];
    Wc[rr * H + c] = acc;
    if (blockIdx.y == 0 && threadIdx.x == 0) {
        float a = 0.f;
        for (int n = 0; n < H; n++) a += Prow[n] * pe2_b[n];
        bc[rr] = a + ((rr < NPREDC) ? pred_b[rr] : ex_b[0]);
    }
}

// ------------------------- fused pair epilogue -------------------------
// grid (ceil(P/16), B*Fh); 256 threads = 8 warps x 2 pairs each.
// z = Sa[b,i] + Sb[b,j] + Sc[b,f]; out = gelu(z) @ Wc^T + bc
__global__ __launch_bounds__(256) void final_kernel(
    const float* __restrict__ Sa, const float* __restrict__ Sb,
    const float* __restrict__ Sc,
    const float* __restrict__ Wc, const float* __restrict__ bc,
    float* __restrict__ out_pred, float* __restrict__ out_ex,
    int Nobj, int P, int Fh)
{
    extern __shared__ float sm[];
    float* Wcs = sm;             // 27*512
    float* Scs = sm + 27 * H;    // 512
    int bf = blockIdx.y;
    int b = bf / Fh;
    int tid = threadIdx.x;

    for (int i = tid; i < 27 * H; i += 256) Wcs[i] = Wc[i];
    for (int i = tid; i < H; i += 256)      Scs[i] = Sc[bf * H + i];
    __syncthreads();

    int w = tid >> 5, lane = tid & 31;
    int p0 = blockIdx.x * 16 + w * 2;
    if (p0 >= P) return;
    int p1 = p0 + 1;
    int nm1 = Nobj - 1;
    int i0 = p0 / nm1, r0 = p0 % nm1; int j0 = (r0 < i0) ? r0 : r0 + 1;
    int i1 = p1 / nm1, r1 = p1 % nm1; int j1 = (r1 < i1) ? r1 : r1 + 1;
    const float* sa0 = Sa + (b * Nobj + i0) * H;
    const float* sb0 = Sb + (b * Nobj + j0) * H;
    const float* sa1 = Sa + (b * Nobj + i1) * H;
    const float* sb1 = Sb + (b * Nobj + j1) * H;

    float acc0[27], acc1[27];
    #pragma unroll
    for (int r = 0; r < 27; r++) { acc0[r] = 0.f; acc1[r] = 0.f; }

    #pragma unroll
    for (int jj = 0; jj < 8; jj++) {
        int m = (lane + jj * 32) * 2;
        float2 a0  = *(const float2*)&sa0[m];
        float2 b0v = *(const float2*)&sb0[m];
        float2 a1  = *(const float2*)&sa1[m];
        float2 b1v = *(const float2*)&sb1[m];
        float2 cc  = *(const float2*)&Scs[m];
        float g0x = gelu_f(a0.x + b0v.x + cc.x);
        float g0y = gelu_f(a0.y + b0v.y + cc.y);
        float g1x = gelu_f(a1.x + b1v.x + cc.x);
        float g1y = gelu_f(a1.y + b1v.y + cc.y);
        #pragma unroll
        for (int r = 0; r < 27; r++) {
            float2 wv = *(const float2*)&Wcs[r * H + m];
            acc0[r] += g0x * wv.x + g0y * wv.y;
            acc1[r] += g1x * wv.x + g1y * wv.y;
        }
    }

    #pragma unroll
    for (int r = 0; r < 27; r++) {
        #pragma unroll
        for (int o = 16; o; o >>= 1) {
            acc0[r] += __shfl_xor_sync(0xffffffffu, acc0[r], o);
            acc1[r] += __shfl_xor_sync(0xffffffffu, acc1[r], o);
        }
    }
    float v0 = 0.f, v1 = 0.f;
    #pragma unroll
    for (int r = 0; r < 27; r++) {
        if (lane == r) { v0 = acc0[r]; v1 = acc1[r]; }
    }
    if (lane < 27) {
        float bb = bc[lane];
        v0 += bb; v1 += bb;
        int base0 = bf * P + p0;
        if (lane < NPREDC) {
            out_pred[base0 * 26 + lane]       = v0;
            out_pred[(base0 + 1) * 26 + lane] = v1;
        } else {
            out_ex[base0]     = v0;
            out_ex[base0 + 1] = v1;
        }
    }
}

// ------------------------- host launcher -------------------------
extern "C" void kernel_launch(void* const* d_in, const int* in_sizes, int n_in,
                              void* d_out, int out_size)
{
    const float* tc       = (const float*)d_in[0];
    const float* objf     = (const float*)d_in[1];
    const float* fq       = (const float*)d_in[2];
    const float* sa_in_w  = (const float*)d_in[3];
    const float* sa_in_b  = (const float*)d_in[4];
    const float* sa_out_w = (const float*)d_in[5];
    const float* sa_out_b = (const float*)d_in[6];
    const float* ca_in_w  = (const float*)d_in[7];
    const float* ca_in_b  = (const float*)d_in[8];
    const float* ca_out_w = (const float*)d_in[9];
    const float* ca_out_b = (const float*)d_in[10];
    const float* ff1_w    = (const float*)d_in[11];
    const float* ff1_b    = (const float*)d_in[12];
    const float* ff2_w    = (const float*)d_in[13];
    const float* ff2_b    = (const float*)d_in[14];
    const float* n1_w     = (const float*)d_in[15];
    const float* n1_b     = (const float*)d_in[16];
    const float* n2_w     = (const float*)d_in[17];
    const float* n2_b     = (const float*)d_in[18];
    const float* n3_w     = (const float*)d_in[19];
    const float* n3_b     = (const float*)d_in[20];
    const float* norm_w   = (const float*)d_in[21];
    const float* norm_b   = (const float*)d_in[22];
    const float* pe1_w    = (const float*)d_in[23];
    const float* pe1_b    = (const float*)d_in[24];
    const float* pe2_w    = (const float*)d_in[25];
    const float* pe2_b    = (const float*)d_in[26];
    const float* pred_w   = (const float*)d_in[27];
    const float* pred_b   = (const float*)d_in[28];
    const float* ex_w     = (const float*)d_in[29];
    const float* ex_b     = (const float*)d_in[30];

    int B    = in_sizes[0] / (TCTX * H);
    int Nobj = in_sizes[1] / (B * H);
    int P    = Nobj * (Nobj - 1);
    int Fh   = out_size / (B * P * (NPREDC + 1));
    int M    = B * Fh;                 // decoder rows (80)

    float *gx, *gqkv, *gkv, *gattno, *gy, *gh, *gctx, *gSa, *gSb, *gSc, *gWc, *gbc;
    cudaGetSymbolAddress((void**)&gx,     g_x);
    cudaGetSymbolAddress((void**)&gqkv,   g_qkv);
    cudaGetSymbolAddress((void**)&gkv,    g_kv);
    cudaGetSymbolAddress((void**)&gattno, g_attno);
    cudaGetSymbolAddress((void**)&gy,     g_y);
    cudaGetSymbolAddress((void**)&gh,     g_h);
    cudaGetSymbolAddress((void**)&gctx,   g_ctx);
    cudaGetSymbolAddress((void**)&gSa,    g_Sa);
    cudaGetSymbolAddress((void**)&gSb,    g_Sb);
    cudaGetSymbolAddress((void**)&gSc,    g_Sc);
    cudaGetSymbolAddress((void**)&gWc,    g_Wc);
    cudaGetSymbolAddress((void**)&gbc,    g_bc);

    bcast_kernel<<<M, 128>>>(fq, gx, Fh);

    for (int l = 0; l < 2; l++) {
        const float* siw = sa_in_w  + (size_t)l * 3 * H * H;
        const float* sib = sa_in_b  + (size_t)l * 3 * H;
        const float* sow = sa_out_w + (size_t)l * H * H;
        const float* sob = sa_out_b + (size_t)l * H;
        const float* ciw = ca_in_w  + (size_t)l * 3 * H * H;
        const float* cib = ca_in_b  + (size_t)l * 3 * H;
        const float* cow = ca_out_w + (size_t)l * H * H;
        const float* cob = ca_out_b + (size_t)l * H;
        const float* f1w = ff1_w    + (size_t)l * FFD * H;
        const float* f1b = ff1_b    + (size_t)l * FFD;
        const float* f2w = ff2_w    + (size_t)l * H * FFD;
        const float* f2b = ff2_b    + (size_t)l * H;

        // self-attention
        gemm_kernel<<<dim3(M / 16, 3 * H / 64), 256>>>(gx, H, siw, H, sib, nullptr, gqkv, 3 * H, H, 0);
        attn_kernel<<<B * NH, 32 * Fh>>>(gqkv, 3 * H, gqkv + H, gqkv + 2 * H, 3 * H, gattno, Fh, Fh);
        gemm_kernel<<<dim3(M / 16, H / 64), 256>>>(gattno, H, sow, H, sob, gx, gy, H, H, 0);
        ln_kernel<<<M, 128>>>(gy, gx, n1_w + l * H, n1_b + l * H);

        // cross-attention
        gemm_kernel<<<dim3(M / 16, H / 64), 256>>>(gx, H, ciw, H, cib, nullptr, gqkv, H, H, 0);
        gemm_kernel<<<dim3(B * TCTX / 16, 2 * H / 64), 256>>>(tc, H, ciw + (size_t)H * H, H, cib + H, nullptr, gkv, 2 * H, H, 0);
        attn_kernel<<<B * NH, 32 * Fh>>>(gqkv, H, gkv, gkv + H, 2 * H, gattno, Fh, TCTX);
        gemm_kernel<<<dim3(M / 16, H / 64), 256>>>(gattno, H, cow, H, cob, gx, gy, H, H, 0);
        ln_kernel<<<M, 128>>>(gy, gx, n2_w + l * H, n2_b + l * H);

        // feed-forward
        gemm_kernel<<<dim3(M / 16, FFD / 64), 256>>>(gx, H, f1w, H, f1b, nullptr, gh, FFD, H, 1);
        gemm_kernel<<<dim3(M / 16, H / 64), 256>>>(gh, FFD, f2w, FFD, f2b, gx, gy, H, FFD, 0);
        ln_kernel<<<M, 128>>>(gy, gx, n3_w + l * H, n3_b + l * H);
    }

    ln_kernel<<<M, 128>>>(gx, gctx, norm_w, norm_b);

    // pe1 factorization: Sa/Sb over object features, Sc over ctx
    gemm_kernel<<<dim3(B * Nobj / 16, H / 64), 256>>>(objf, H, pe1_w,         3 * H, nullptr, nullptr, gSa, H, H, 0);
    gemm_kernel<<<dim3(B * Nobj / 16, H / 64), 256>>>(objf, H, pe1_w + H,     3 * H, nullptr, nullptr, gSb, H, H, 0);
    gemm_kernel<<<dim3(M / 16,        H / 64), 256>>>(gctx, H, pe1_w + 2 * H, 3 * H, pe1_b,   nullptr, gSc, H, H, 0);

    // fold pe2 into pred/ex
    wc_kernel<<<dim3(27, H / 64), 64>>>(pred_w, pred_b, ex_w, ex_b, pe2_w, pe2_b, gWc, gbc);

    // fused pair epilogue
    size_t shm = (size_t)(27 * H + H) * sizeof(float);
    cudaFuncSetAttribute(final_kernel, cudaFuncAttributeMaxDynamicSharedMemorySize, (int)shm);
    float* out_pred = (float*)d_out;
    float* out_ex   = out_pred + (size_t)B * Fh * P * NPREDC;
    final_kernel<<<dim3((P + 15) / 16, M), 256, shm>>>(gSa, gSb, gSc, gWc, gbc,
                                                       out_pred, out_ex, Nobj, P, Fh);
}

// round 3
// speedup vs baseline: 1.0012x; 1.0012x over previous
#include <cuda_runtime.h>
#include <cuda_bf16.h>
#include <math.h>

#define H    512
#define NH   8
#define DH   64
#define TCTX 10
#define FFD  2048
#define NPREDC 26
#define MAXB 16
#define MAXF 5

// ------------------------- device scratch -------------------------
__device__ float g_x    [MAXB * MAXF * H];
__device__ float g_qkv  [MAXB * MAXF * 3 * H];
__device__ float g_kv   [MAXB * TCTX * 2 * H];
__device__ float g_attno[MAXB * MAXF * H];
__device__ float g_y    [MAXB * MAXF * H];
__device__ float g_h    [MAXB * MAXF * FFD];
__device__ float g_ctx  [MAXB * MAXF * H];
__device__ float g_Sa   [MAXB * 20 * H];
__device__ float g_Sb   [MAXB * 20 * H];
__device__ float g_Sc   [MAXB * MAXF * H];
__device__ float g_Wc   [27 * H];
__device__ float g_bc   [27];

__device__ __forceinline__ float gelu_f(float x) {
    return 0.5f * x * (1.0f + erff(x * 0.70710678118654752440f));
}

// ------------------------- broadcast queries -------------------------
__global__ void bcast_kernel(const float* __restrict__ fq, float* __restrict__ x, int Fh) {
    int row = blockIdx.x;          // b*Fh + f
    int f = row % Fh;
    int tid = threadIdx.x;         // 128
    #pragma unroll
    for (int i = 0; i < 4; i++) {
        int c = tid + i * 128;
        x[row * H + c] = fq[f * H + c];
    }
}

// ------------------------- generic GEMM: C = A @ W^T (+bias)(+act)(+res) ----
// A: (M,K) lda; W: (N,K) row-major with row stride ldw; C: (M,N) ldc
// grid (M/16, N/64), 256 threads. M%16==0, N%64==0, K%32==0 guaranteed.
__global__ __launch_bounds__(256) void gemm_kernel(
    const float* __restrict__ A, int lda,
    const float* __restrict__ W, int ldw,
    const float* __restrict__ bias,
    const float* __restrict__ res,
    float* __restrict__ C, int ldc,
    int K, int act)
{
    __shared__ float As[16][33];
    __shared__ float Ws[64][33];
    int tid = threadIdx.x;
    int row0 = blockIdx.x * 16;
    int n0   = blockIdx.y * 64;
    int r  = tid >> 4;            // 0..15
    int c0 = (tid & 15) << 2;     // 0..60
    int ar = tid >> 4;
    int ak = (tid & 15) << 1;
    float acc0 = 0.f, acc1 = 0.f, acc2 = 0.f, acc3 = 0.f;

    for (int k0 = 0; k0 < K; k0 += 32) {
        float2 av = *(const float2*)&A[(row0 + ar) * lda + k0 + ak];
        As[ar][ak]     = av.x;
        As[ar][ak + 1] = av.y;
        #pragma unroll
        for (int q = 0; q < 4; q++) {
            int f2 = q * 256 + tid;
            int wn = f2 >> 4;
            int wk = (f2 & 15) << 1;
            float2 wv = *(const float2*)&W[(n0 + wn) * ldw + k0 + wk];
            Ws[wn][wk]     = wv.x;
            Ws[wn][wk + 1] = wv.y;
        }
        __syncthreads();
        #pragma unroll
        for (int kk = 0; kk < 32; kk++) {
            float a = As[r][kk];
            acc0 += a * Ws[c0    ][kk];
            acc1 += a * Ws[c0 + 1][kk];
            acc2 += a * Ws[c0 + 2][kk];
            acc3 += a * Ws[c0 + 3][kk];
        }
        __syncthreads();
    }

    int row = row0 + r;
    float v[4] = {acc0, acc1, acc2, acc3};
    #pragma unroll
    for (int j = 0; j < 4; j++) {
        int n = n0 + c0 + j;
        float x = v[j];
        if (bias) x += bias[n];
        if (act == 1) x = gelu_f(x);
        if (res) x += res[row * ldc + n];
        C[row * ldc + n] = x;
    }
}

// ------------------------- attention (tiny T) -------------------------
// grid = B*NH blocks; block = 32*Tq threads; warp qi handles query row qi.
// q row index = b*Tq+qi (stride ldq); kv row index = b*Tk+k (stride ldkv).
__global__ void attn_kernel(
    const float* __restrict__ Q, int ldq,
    const float* __restrict__ Kp, const float* __restrict__ Vp, int ldkv,
    float* __restrict__ O, int Tq, int Tk)
{
    int b = blockIdx.x / NH;
    int h = blockIdx.x % NH;
    int qi = threadIdx.x >> 5;
    int lane = threadIdx.x & 31;

    const float* qrow = Q + (b * Tq + qi) * ldq + h * DH;
    float q0 = qrow[lane], q1 = qrow[lane + 32];

    float s[TCTX];
    #pragma unroll
    for (int k = 0; k < TCTX; k++) {
        if (k < Tk) {
            const float* krow = Kp + (b * Tk + k) * ldkv + h * DH;
            float p = q0 * krow[lane] + q1 * krow[lane + 32];
            #pragma unroll
            for (int off = 16; off; off >>= 1) p += __shfl_xor_sync(0xffffffffu, p, off);
            s[k] = p * 0.125f;   // 1/sqrt(64)
        }
    }
    float mx = -1e30f;
    #pragma unroll
    for (int k = 0; k < TCTX; k++) if (k < Tk) mx = fmaxf(mx, s[k]);
    float sum = 0.f;
    #pragma unroll
    for (int k = 0; k < TCTX; k++) if (k < Tk) { s[k] = expf(s[k] - mx); sum += s[k]; }
    float inv = 1.f / sum;
    float o0 = 0.f, o1 = 0.f;
    #pragma unroll
    for (int k = 0; k < TCTX; k++) {
        if (k < Tk) {
            const float* vrow = Vp + (b * Tk + k) * ldkv + h * DH;
            float a = s[k] * inv;
            o0 += a * vrow[lane];
            o1 += a * vrow[lane + 32];
        }
    }
    float* orow = O + (b * Tq + qi) * H + h * DH;
    orow[lane]      = o0;
    orow[lane + 32] = o1;
}

// ------------------------- row LayerNorm (H=512) -------------------------
__global__ void ln_kernel(const float* __restrict__ src, float* __restrict__ dst,
                          const float* __restrict__ w, const float* __restrict__ b)
{
    __shared__ float red[4];
    int row = blockIdx.x;
    int tid = threadIdx.x;         // 128
    int lane = tid & 31, wid = tid >> 5;
    const float* x = src + row * H;

    float v[4];
    float s = 0.f;
    #pragma unroll
    for (int i = 0; i < 4; i++) { v[i] = x[tid + i * 128]; s += v[i]; }
    #pragma unroll
    for (int o = 16; o; o >>= 1) s += __shfl_xor_sync(0xffffffffu, s, o);
    if (lane == 0) red[wid] = s;
    __syncthreads();
    float mean = (red[0] + red[1] + red[2] + red[3]) * (1.0f / H);
    __syncthreads();

    float q = 0.f;
    #pragma unroll
    for (int i = 0; i < 4; i++) { float d = v[i] - mean; q += d * d; }
    #pragma unroll
    for (int o = 16; o; o >>= 1) q += __shfl_xor_sync(0xffffffffu, q, o);
    if (lane == 0) red[wid] = q;
    __syncthreads();
    float var = (red[0] + red[1] + red[2] + red[3]) * (1.0f / H);
    float inv = 1.0f / sqrtf(var + 1e-5f);

    #pragma unroll
    for (int i = 0; i < 4; i++) {
        int c = tid + i * 128;
        dst[row * H + c] = (v[i] - mean) * inv * w[c] + b[c];
    }
}

// ------------------------- Wc = [pred_w;ex_w] @ pe2_w, bc fold ------------
__global__ void wc_kernel(const float* __restrict__ pred_w, const float* __restrict__ pred_b,
                          const float* __restrict__ ex_w, const float* __restrict__ ex_b,
                          const float* __restrict__ pe2_w, const float* __restrict__ pe2_b,
                          float* __restrict__ Wc, float* __restrict__ bc)
{
    int rr = blockIdx.x;                       // 0..26
    int c = blockIdx.y * 64 + threadIdx.x;     // 0..511
    const float* Prow = (rr < NPREDC) ? (pred_w + rr * H) : ex_w;
    float acc = 0.f;
    for (int n = 0; n < H; n++) acc += Prow[n] * pe2_w[n * H + c];
    Wc[rr * H + c] = acc;
    if (blockIdx.y == 0 && threadIdx.x == 0) {
        float a = 0.f;
        for (int n = 0; n < H; n++) a += Prow[n] * pe2_b[n];
        bc[rr] = a + ((rr < NPREDC) ? pred_b[rr] : ex_b[0]);
    }
}

// ------------------------- fused pair epilogue -------------------------
// grid (ceil(P/16), B*Fh); 256 threads = 8 warps x 2 pairs each.
// z = Sa[b,i] + Sb[b,j] + Sc[b,f]; out = gelu(z) @ Wc^T + bc
__global__ __launch_bounds__(256) void final_kernel(
    const float* __restrict__ Sa, const float* __restrict__ Sb,
    const float* __restrict__ Sc,
    const float* __restrict__ Wc, const float* __restrict__ bc,
    float* __restrict__ out_pred, float* __restrict__ out_ex,
    int Nobj, int P, int Fh)
{
    extern __shared__ float sm[];
    float* Wcs = sm;             // 27*512
    float* Scs = sm + 27 * H;    // 512
    int bf = blockIdx.y;
    int b = bf / Fh;
    int tid = threadIdx.x;

    for (int i = tid; i < 27 * H; i += 256) Wcs[i] = Wc[i];
    for (int i = tid; i < H; i += 256)      Scs[i] = Sc[bf * H + i];
    __syncthreads();

    int w = tid >> 5, lane = tid & 31;
    int p0 = blockIdx.x * 16 + w * 2;
    if (p0 >= P) return;
    int p1 = p0 + 1;
    int nm1 = Nobj - 1;
    int i0 = p0 / nm1, r0 = p0 % nm1; int j0 = (r0 < i0) ? r0 : r0 + 1;
    int i1 = p1 / nm1, r1 = p1 % nm1; int j1 = (r1 < i1) ? r1 : r1 + 1;
    const float* sa0 = Sa + (b * Nobj + i0) * H;
    const float* sb0 = Sb + (b * Nobj + j0) * H;
    const float* sa1 = Sa + (b * Nobj + i1) * H;
    const float* sb1 = Sb + (b * Nobj + j1) * H;

    float acc0[27], acc1[27];
    #pragma unroll
    for (int r = 0; r < 27; r++) { acc0[r] = 0.f; acc1[r] = 0.f; }

    #pragma unroll
    for (int jj = 0; jj < 8; jj++) {
        int m = (lane + jj * 32) * 2;
        float2 a0  = *(const float2*)&sa0[m];
        float2 b0v = *(const float2*)&sb0[m];
        float2 a1  = *(const float2*)&sa1[m];
        float2 b1v = *(const float2*)&sb1[m];
        float2 cc  = *(const float2*)&Scs[m];
        float g0x = gelu_f(a0.x + b0v.x + cc.x);
        float g0y = gelu_f(a0.y + b0v.y + cc.y);
        float g1x = gelu_f(a1.x + b1v.x + cc.x);
        float g1y = gelu_f(a1.y + b1v.y + cc.y);
        #pragma unroll
        for (int r = 0; r < 27; r++) {
            float2 wv = *(const float2*)&Wcs[r * H + m];
            acc0[r] += g0x * wv.x + g0y * wv.y;
            acc1[r] += g1x * wv.x + g1y * wv.y;
        }
    }

    #pragma unroll
    for (int r = 0; r < 27; r++) {
        #pragma unroll
        for (int o = 16; o; o >>= 1) {
            acc0[r] += __shfl_xor_sync(0xffffffffu, acc0[r], o);
            acc1[r] += __shfl_xor_sync(0xffffffffu, acc1[r], o);
        }
    }
    float v0 = 0.f, v1 = 0.f;
    #pragma unroll
    for (int r = 0; r < 27; r++) {
        if (lane == r) { v0 = acc0[r]; v1 = acc1[r]; }
    }
    if (lane < 27) {
        float bb = bc[lane];
        v0 += bb; v1 += bb;
        int base0 = bf * P + p0;
        if (lane < NPREDC) {
            out_pred[base0 * 26 + lane]       = v0;
            out_pred[(base0 + 1) * 26 + lane] = v1;
        } else {
            out_ex[base0]     = v0;
            out_ex[base0 + 1] = v1;
        }
    }
}

// ------------------------- host launcher -------------------------
extern "C" void kernel_launch(void* const* d_in, const int* in_sizes, int n_in,
                              void* d_out, int out_size)
{
    const float* tc       = (const float*)d_in[0];
    const float* objf     = (const float*)d_in[1];
    const float* fq       = (const float*)d_in[2];
    const float* sa_in_w  = (const float*)d_in[3];
    const float* sa_in_b  = (const float*)d_in[4];
    const float* sa_out_w = (const float*)d_in[5];
    const float* sa_out_b = (const float*)d_in[6];
    const float* ca_in_w  = (const float*)d_in[7];
    const float* ca_in_b  = (const float*)d_in[8];
    const float* ca_out_w = (const float*)d_in[9];
    const float* ca_out_b = (const float*)d_in[10];
    const float* ff1_w    = (const float*)d_in[11];
    const float* ff1_b    = (const float*)d_in[12];
    const float* ff2_w    = (const float*)d_in[13];
    const float* ff2_b    = (const float*)d_in[14];
    const float* n1_w     = (const float*)d_in[15];
    const float* n1_b     = (const float*)d_in[16];
    const float* n2_w     = (const float*)d_in[17];
    const float* n2_b     = (const float*)d_in[18];
    const float* n3_w     = (const float*)d_in[19];
    const float* n3_b     = (const float*)d_in[20];
    const float* norm_w   = (const float*)d_in[21];
    const float* norm_b   = (const float*)d_in[22];
    const float* pe1_w    = (const float*)d_in[23];
    const float* pe1_b    = (const float*)d_in[24];
    const float* pe2_w    = (const float*)d_in[25];
    const float* pe2_b    = (const float*)d_in[26];
    const float* pred_w   = (const float*)d_in[27];
    const float* pred_b   = (const float*)d_in[28];
    const float* ex_w     = (const float*)d_in[29];
    const float* ex_b     = (const float*)d_in[30];

    int B    = in_sizes[0] / (TCTX * H);
    int Nobj = in_sizes[1] / (B * H);
    int P    = Nobj * (Nobj - 1);
    int Fh   = out_size / (B * P * (NPREDC + 1));
    int M    = B * Fh;                 // decoder rows (80)

    float *gx, *gqkv, *gkv, *gattno, *gy, *gh, *gctx, *gSa, *gSb, *gSc, *gWc, *gbc;
    cudaGetSymbolAddress((void**)&gx,     g_x);
    cudaGetSymbolAddress((void**)&gqkv,   g_qkv);
    cudaGetSymbolAddress((void**)&gkv,    g_kv);
    cudaGetSymbolAddress((void**)&gattno, g_attno);
    cudaGetSymbolAddress((void**)&gy,     g_y);
    cudaGetSymbolAddress((void**)&gh,     g_h);
    cudaGetSymbolAddress((void**)&gctx,   g_ctx);
    cudaGetSymbolAddress((void**)&gSa,    g_Sa);
    cudaGetSymbolAddress((void**)&gSb,    g_Sb);
    cudaGetSymbolAddress((void**)&gSc,    g_Sc);
    cudaGetSymbolAddress((void**)&gWc,    g_Wc);
    cudaGetSymbolAddress((void**)&gbc,    g_bc);

    bcast_kernel<<<M, 128>>>(fq, gx, Fh);

    for (int l = 0; l < 2; l++) {
        const float* siw = sa_in_w  + (size_t)l * 3 * H * H;
        const float* sib = sa_in_b  + (size_t)l * 3 * H;
        const float* sow = sa_out_w + (size_t)l * H * H;
        const float* sob = sa_out_b + (size_t)l * H;
        const float* ciw = ca_in_w  + (size_t)l * 3 * H * H;
        const float* cib = ca_in_b  + (size_t)l * 3 * H;
        const float* cow = ca_out_w + (size_t)l * H * H;
        const float* cob = ca_out_b + (size_t)l * H;
        const float* f1w = ff1_w    + (size_t)l * FFD * H;
        const float* f1b = ff1_b    + (size_t)l * FFD;
        const float* f2w = ff2_w    + (size_t)l * H * FFD;
        const float* f2b = ff2_b    + (size_t)l * H;

        // self-attention
        gemm_kernel<<<dim3(M / 16, 3 * H / 64), 256>>>(gx, H, siw, H, sib, nullptr, gqkv, 3 * H, H, 0);
        attn_kernel<<<B * NH, 32 * Fh>>>(gqkv, 3 * H, gqkv + H, gqkv + 2 * H, 3 * H, gattno, Fh, Fh);
        gemm_kernel<<<dim3(M / 16, H / 64), 256>>>(gattno, H, sow, H, sob, gx, gy, H, H, 0);
        ln_kernel<<<M, 128>>>(gy, gx, n1_w + l * H, n1_b + l * H);

        // cross-attention
        gemm_kernel<<<dim3(M / 16, H / 64), 256>>>(gx, H, ciw, H, cib, nullptr, gqkv, H, H, 0);
        gemm_kernel<<<dim3(B * TCTX / 16, 2 * H / 64), 256>>>(tc, H, ciw + (size_t)H * H, H, cib + H, nullptr, gkv, 2 * H, H, 0);
        attn_kernel<<<B * NH, 32 * Fh>>>(gqkv, H, gkv, gkv + H, 2 * H, gattno, Fh, TCTX);
        gemm_kernel<<<dim3(M / 16, H / 64), 256>>>(gattno, H, cow, H, cob, gx, gy, H, H, 0);
        ln_kernel<<<M, 128>>>(gy, gx, n2_w + l * H, n2_b + l * H);

        // feed-forward
        gemm_kernel<<<dim3(M / 16, FFD / 64), 256>>>(gx, H, f1w, H, f1b, nullptr, gh, FFD, H, 1);
        gemm_kernel<<<dim3(M / 16, H / 64), 256>>>(gh, FFD, f2w, FFD, f2b, gx, gy, H, FFD, 0);
        ln_kernel<<<M, 128>>>(gy, gx, n3_w + l * H, n3_b + l * H);
    }

    ln_kernel<<<M, 128>>>(gx, gctx, norm_w, norm_b);

    // pe1 factorization: Sa/Sb over object features, Sc over ctx
    gemm_kernel<<<dim3(B * Nobj / 16, H / 64), 256>>>(objf, H, pe1_w,         3 * H, nullptr, nullptr, gSa, H, H, 0);
    gemm_kernel<<<dim3(B * Nobj / 16, H / 64), 256>>>(objf, H, pe1_w + H,     3 * H, nullptr, nullptr, gSb, H, H, 0);
    gemm_kernel<<<dim3(M / 16,        H / 64), 256>>>(gctx, H, pe1_w + 2 * H, 3 * H, pe1_b,   nullptr, gSc, H, H, 0);

    // fold pe2 into pred/ex
    wc_kernel<<<dim3(27, H / 64), 64>>>(pred_w, pred_b, ex_w, ex_b, pe2_w, pe2_b, gWc, gbc);

    // fused pair epilogue
    size_t shm = (size_t)(27 * H + H) * sizeof(float);
    cudaFuncSetAttribute(final_kernel, cudaFuncAttributeMaxDynamicSharedMemorySize, (int)shm);
    float* out_pred = (float*)d_out;
    float* out_ex   = out_pred + (size_t)B * Fh * P * NPREDC;
    final_kernel<<<dim3((P + 15) / 16, M), 256, shm>>>(gSa, gSb, gSc, gWc, gbc,
                                                       out_pred, out_ex, Nobj, P, Fh);
}